// round 8
// baseline (speedup 1.0000x reference)
#include <cuda_runtime.h>
#include <cuda_bf16.h>

// EdgeAtt fused via per-batch atomic flags: B=64, L=512, D=512
// 512 CTAs; CTA (b,c) does projections for rows [c*64,c*64+64) of batch b,
// signals cnt[b], spins for 8 arrivals, then softmax+store for same rows.

#define L_DIM 512
#define D_DIM 512
#define SLOPE 0.2f
#define MASKV -1e9f

__device__ float g_ei[64 * L_DIM];
__device__ float g_ej[64 * L_DIM];
__device__ int   g_cnt[64];

__global__ void k_reset() { g_cnt[threadIdx.x] = 0; }

__global__ void __launch_bounds__(256, 4)
k_fused(const float* __restrict__ nf, const float* __restrict__ wa,
        const float* __restrict__ ba, const int* __restrict__ tlen,
        float* __restrict__ out)
{
    __shared__ float sf1[L_DIM];
    __shared__ float sf2[L_DIM];
    __shared__ float smax[8];

    const int tid  = threadIdx.x;
    const int warp = tid >> 5;
    const int lane = tid & 31;
    const int b    = blockIdx.x >> 3;
    const int c    = blockIdx.x & 7;
    const int row0 = c * 64;
    const int len  = __ldg(&tlen[b]);

    // ---------------- phase 1: projections for rows [row0, row0+64) ----------------
    const float4* w1 = reinterpret_cast<const float4*>(wa);
    const float4* w2 = reinterpret_cast<const float4*>(wa + D_DIM);
    {
        const int lr0 = warp * 8;                      // each warp: 8 rows
        for (int k = 0; k < 8; k++) {
            const int l = row0 + lr0 + k;              // global row in batch
            if (l >= len) break;                       // unused projections (rows ascend)
            const int r = b * L_DIM + l;
            const float4* row = reinterpret_cast<const float4*>(nf + (size_t)r * D_DIM);
            float s1 = 0.f, s2 = 0.f;
#pragma unroll
            for (int t = 0; t < 4; t++) {
                int idx = lane + t * 32;
                float4 v = row[idx];
                float4 a = __ldg(&w1[idx]);
                float4 w = __ldg(&w2[idx]);
                s1 += v.x * a.x + v.y * a.y + v.z * a.z + v.w * a.w;
                s2 += v.x * w.x + v.y * w.y + v.z * w.z + v.w * w.w;
            }
#pragma unroll
            for (int o = 16; o; o >>= 1) {
                s1 += __shfl_xor_sync(0xffffffffu, s1, o);
                s2 += __shfl_xor_sync(0xffffffffu, s2, o);
            }
            if (lane == 0) { g_ei[r] = s1; g_ej[r] = s2; }
        }
    }

    // release: our slice's writes visible, then count in
    __threadfence();
    __syncthreads();
    if (tid == 0) {
        atomicAdd(&g_cnt[b], 1);
        // acquire-spin until whole batch done
        int v;
        do {
            asm volatile("ld.global.acquire.gpu.b32 %0, [%1];"
                         : "=r"(v) : "l"(&g_cnt[b]) : "memory");
        } while (v < 8);
    }
    __syncthreads();

    // ---------------- phase 2: masked softmax for same 64 rows ----------------
    const float v0 = (tid       < len) ? g_ej[b * L_DIM + tid]       : MASKV;
    const float v1 = (tid + 256 < len) ? g_ej[b * L_DIM + tid + 256] : MASKV;

    float mv = fmaxf(v0, v1);
#pragma unroll
    for (int o = 16; o; o >>= 1) mv = fmaxf(mv, __shfl_xor_sync(0xffffffffu, mv, o));
    if (lane == 0) smax[warp] = mv;
    __syncthreads();
    float mxej = smax[0];
#pragma unroll
    for (int k = 1; k < 8; k++) mxej = fmaxf(mxej, smax[k]);

    // factorization tables over leaky_relu pieces (exponents <= 0; masked j -> 0)
    sf1[tid]       = __expf(v0 - mxej);
    sf1[tid + 256] = __expf(v1 - mxej);
    sf2[tid]       = __expf(SLOPE * (v0 - mxej));
    sf2[tid + 256] = __expf(SLOPE * (v1 - mxej));
    __syncthreads();

    float4 f1c[4], f2c[4];
#pragma unroll
    for (int t = 0; t < 4; t++) {
        const int j0 = t * 128 + lane * 4;
        f1c[t] = *reinterpret_cast<const float4*>(&sf1[j0]);
        f2c[t] = *reinterpret_cast<const float4*>(&sf2[j0]);
    }

    const float bias = __ldg(ba);
    const float* gei = g_ei + b * L_DIM;
    float* obase = out + ((size_t)b * L_DIM + row0) * L_DIM;

#pragma unroll
    for (int t8 = 0; t8 < 8; t8++) {
        const int lr = warp * 8 + t8;
        const int i  = row0 + lr;
        float4* orow4 = reinterpret_cast<float4*>(obase + (size_t)lr * L_DIM);

        if (i >= len) {
            float4 z = make_float4(0.f, 0.f, 0.f, 0.f);
#pragma unroll
            for (int t = 0; t < 4; t++) orow4[t * 32 + lane] = z;
            continue;
        }

        const float ei   = gei[i] + bias;
        const float mraw = ei + mxej;
        const float m    = fmaxf(mraw, SLOPE * mraw);   // exact row max
        const float E1   = __expf(mraw - m);
        const float E2   = __expf(SLOPE * mraw - m);
        const float T    = __expf(-ei - mxej);          // f1 > T <=> ei+ej > 0

        float4 p[4];
        float s = 0.f;
#pragma unroll
        for (int t = 0; t < 4; t++) {
            float pe;
            pe = (f1c[t].x > T) ? f1c[t].x * E1 : f2c[t].x * E2; p[t].x = pe; s += pe;
            pe = (f1c[t].y > T) ? f1c[t].y * E1 : f2c[t].y * E2; p[t].y = pe; s += pe;
            pe = (f1c[t].z > T) ? f1c[t].z * E1 : f2c[t].z * E2; p[t].z = pe; s += pe;
            pe = (f1c[t].w > T) ? f1c[t].w * E1 : f2c[t].w * E2; p[t].w = pe; s += pe;
        }
#pragma unroll
        for (int o = 16; o; o >>= 1) s += __shfl_xor_sync(0xffffffffu, s, o);

        const float inv = 1.f / s;
#pragma unroll
        for (int t = 0; t < 4; t++) {
            float4 r;
            r.x = p[t].x * inv; r.y = p[t].y * inv;
            r.z = p[t].z * inv; r.w = p[t].w * inv;
            orow4[t * 32 + lane] = r;
        }
    }
}

extern "C" void kernel_launch(void* const* d_in, const int* in_sizes, int n_in,
                              void* d_out, int out_size) {
    const float* nf   = (const float*)d_in[0];   // [B, L, D]
    const float* wa   = (const float*)d_in[1];   // [2D]
    const float* ba   = (const float*)d_in[2];   // [1]
    const int*   tlen = (const int*)d_in[3];     // [B]
    float* out = (float*)d_out;                  // [B, L, L]

    const int B = in_sizes[3];
    k_reset<<<1, B>>>();
    k_fused<<<B * 8, 256>>>(nf, wa, ba, tlen, out);
}

// round 9
// speedup vs baseline: 1.1278x; 1.1278x over previous
#include <cuda_runtime.h>
#include <cuda_bf16.h>

// EdgeAtt: B=64, L=512, D=512  (two-kernel; fusion regressed twice)
// k_proj: early-exit on unused rows. k_soft: premasked e_j + analytic row
// max (leaky_relu monotonic) + MUFU exp, warp per row, grid (L/8, B).

#define L_DIM 512
#define D_DIM 512
#define SLOPE 0.2f
#define MASKV -1e9f

__device__ float g_ei[64 * L_DIM];
__device__ float g_ej[64 * L_DIM];

// ---------------- kernel 1: dual projection, warp per row ----------------
__global__ void __launch_bounds__(256) k_proj(const float* __restrict__ nf,
                                              const float* __restrict__ wa,
                                              const int* __restrict__ tlen,
                                              int n_rows) {
    int r = (blockIdx.x * blockDim.x + threadIdx.x) >> 5;
    int lane = threadIdx.x & 31;
    if (r >= n_rows) return;
    const int b = r >> 9;
    const int l = r & (L_DIM - 1);
    if (l >= __ldg(&tlen[b])) return;   // projection never consumed

    const float4* row = reinterpret_cast<const float4*>(nf + (size_t)r * D_DIM);
    const float4* w1  = reinterpret_cast<const float4*>(wa);
    const float4* w2  = reinterpret_cast<const float4*>(wa + D_DIM);

    float s1 = 0.f, s2 = 0.f;
#pragma unroll
    for (int t = 0; t < 4; t++) {
        int idx = lane + t * 32;
        float4 v = row[idx];
        float4 a = __ldg(&w1[idx]);
        float4 w = __ldg(&w2[idx]);
        s1 += v.x * a.x + v.y * a.y + v.z * a.z + v.w * a.w;
        s2 += v.x * w.x + v.y * w.y + v.z * w.z + v.w * w.w;
    }
#pragma unroll
    for (int o = 16; o; o >>= 1) {
        s1 += __shfl_xor_sync(0xffffffffu, s1, o);
        s2 += __shfl_xor_sync(0xffffffffu, s2, o);
    }
    if (lane == 0) {
        g_ei[r] = s1;
        g_ej[r] = s2;
    }
}

// ---------------- kernel 2: masked softmax, warp per output row ----------------
__global__ void __launch_bounds__(256) k_soft(const float* __restrict__ ba,
                                              const int* __restrict__ tlen,
                                              float* __restrict__ out) {
    __shared__ float sej[L_DIM];
    __shared__ float smax[8];

    const int b    = blockIdx.y;
    const int tid  = threadIdx.x;
    const int warp = tid >> 5;
    const int lane = tid & 31;
    const int len  = tlen[b];

    // premasked e_j: j>=len -> -1e9, so exp underflows to exact 0 later
    const float v0 = (tid       < len) ? g_ej[b * L_DIM + tid]       : MASKV;
    const float v1 = (tid + 256 < len) ? g_ej[b * L_DIM + tid + 256] : MASKV;
    sej[tid]       = v0;
    sej[tid + 256] = v1;

    // block max of premasked e_j (len >= 1 so a real value wins)
    float mv = fmaxf(v0, v1);
#pragma unroll
    for (int o = 16; o; o >>= 1) mv = fmaxf(mv, __shfl_xor_sync(0xffffffffu, mv, o));
    if (lane == 0) smax[warp] = mv;
    __syncthreads();
    float mxej = smax[0];
#pragma unroll
    for (int k = 1; k < 8; k++) mxej = fmaxf(mxej, smax[k]);

    const int i = blockIdx.x * 8 + warp;
    float4* orow4 = reinterpret_cast<float4*>(out + ((size_t)b * L_DIM + i) * L_DIM);

    if (i >= len) {
        float4 z = make_float4(0.f, 0.f, 0.f, 0.f);
#pragma unroll
        for (int t = 0; t < 4; t++) orow4[t * 32 + lane] = z;
        return;
    }

    const float ei   = g_ei[b * L_DIM + i] + __ldg(ba);
    const float mraw = ei + mxej;
    const float m    = fmaxf(mraw, SLOPE * mraw);   // exact row max (monotonic lrelu)

    float4 p[4];
    float s = 0.f;
#pragma unroll
    for (int t = 0; t < 4; t++) {
        const int j0 = t * 128 + lane * 4;
        float4 e4 = *reinterpret_cast<const float4*>(&sej[j0]);

        float v, lr, pe;
        v = ei + e4.x; lr = fmaxf(v, SLOPE * v);
        pe = __expf(lr - m); p[t].x = pe; s += pe;
        v = ei + e4.y; lr = fmaxf(v, SLOPE * v);
        pe = __expf(lr - m); p[t].y = pe; s += pe;
        v = ei + e4.z; lr = fmaxf(v, SLOPE * v);
        pe = __expf(lr - m); p[t].z = pe; s += pe;
        v = ei + e4.w; lr = fmaxf(v, SLOPE * v);
        pe = __expf(lr - m); p[t].w = pe; s += pe;
    }
#pragma unroll
    for (int o = 16; o; o >>= 1) s += __shfl_xor_sync(0xffffffffu, s, o);

    const float inv = 1.f / s;
#pragma unroll
    for (int t = 0; t < 4; t++) {
        float4 r;
        r.x = p[t].x * inv; r.y = p[t].y * inv;
        r.z = p[t].z * inv; r.w = p[t].w * inv;
        orow4[t * 32 + lane] = r;
    }
}

extern "C" void kernel_launch(void* const* d_in, const int* in_sizes, int n_in,
                              void* d_out, int out_size) {
    const float* nf   = (const float*)d_in[0];   // [B, L, D]
    const float* wa   = (const float*)d_in[1];   // [2D]
    const float* ba   = (const float*)d_in[2];   // [1]
    const int*   tlen = (const int*)d_in[3];     // [B]
    float* out = (float*)d_out;                  // [B, L, L]

    const int B = in_sizes[3];
    const int n_rows = B * L_DIM;

    k_proj<<<(n_rows + 7) / 8, 256>>>(nf, wa, tlen, n_rows);

    dim3 grid(L_DIM / 8, B);
    k_soft<<<grid, 256>>>(ba, tlen, out);
}

// round 10
// speedup vs baseline: 1.2397x; 1.0992x over previous
#include <cuda_runtime.h>
#include <cuda_bf16.h>

// EdgeAtt: B=64, L=512, D=512. Two kernels + PDL overlap:
// k_soft's zero-rows (i>=len, ~half the 67MB output) are independent of
// k_proj and are written before cudaGridDependencySynchronize().

#define L_DIM 512
#define D_DIM 512
#define SLOPE 0.2f
#define MASKV -1e9f

__device__ float g_ei[64 * L_DIM];
__device__ float g_ej[64 * L_DIM];

// ---------------- kernel 1: dual projection, warp per row ----------------
__global__ void __launch_bounds__(256) k_proj(const float* __restrict__ nf,
                                              const float* __restrict__ wa,
                                              const int* __restrict__ tlen,
                                              int n_rows) {
    // allow the dependent k_soft to begin its independent prologue now
    cudaTriggerProgrammaticLaunchCompletion();

    int r = (blockIdx.x * blockDim.x + threadIdx.x) >> 5;
    int lane = threadIdx.x & 31;
    if (r >= n_rows) return;
    const int b = r >> 9;
    const int l = r & (L_DIM - 1);
    if (l >= __ldg(&tlen[b])) return;   // projection never consumed

    const float4* row = reinterpret_cast<const float4*>(nf + (size_t)r * D_DIM);
    const float4* w1  = reinterpret_cast<const float4*>(wa);
    const float4* w2  = reinterpret_cast<const float4*>(wa + D_DIM);

    float s1 = 0.f, s2 = 0.f;
#pragma unroll
    for (int t = 0; t < 4; t++) {
        int idx = lane + t * 32;
        float4 v = row[idx];
        float4 a = __ldg(&w1[idx]);
        float4 w = __ldg(&w2[idx]);
        s1 += v.x * a.x + v.y * a.y + v.z * a.z + v.w * a.w;
        s2 += v.x * w.x + v.y * w.y + v.z * w.z + v.w * w.w;
    }
#pragma unroll
    for (int o = 16; o; o >>= 1) {
        s1 += __shfl_xor_sync(0xffffffffu, s1, o);
        s2 += __shfl_xor_sync(0xffffffffu, s2, o);
    }
    if (lane == 0) {
        g_ei[r] = s1;
        g_ej[r] = s2;
    }
}

// ---------------- kernel 2: masked softmax, warp per output row ----------------
__global__ void __launch_bounds__(256) k_soft(const float* __restrict__ ba,
                                              const int* __restrict__ tlen,
                                              float* __restrict__ out) {
    __shared__ float sej[L_DIM];
    __shared__ float smax[8];

    const int b    = blockIdx.y;
    const int tid  = threadIdx.x;
    const int warp = tid >> 5;
    const int lane = tid & 31;
    const int len  = __ldg(&tlen[b]);          // input only: no dependency
    const int i    = blockIdx.x * 8 + warp;

    float4* orow4 = reinterpret_cast<float4*>(out + ((size_t)b * L_DIM + i) * L_DIM);

    // ---- independent prologue: zero rows (runs while k_proj streams) ----
    if (i >= len) {
        float4 z = make_float4(0.f, 0.f, 0.f, 0.f);
#pragma unroll
        for (int t = 0; t < 4; t++) orow4[t * 32 + lane] = z;
        if (blockIdx.x * 8 >= len) return;      // whole CTA invalid: exit w/o sync
    }

    // ---- wait for k_proj results ----
    cudaGridDependencySynchronize();

    // premasked e_j: j>=len -> -1e9 (exp underflows to exact 0)
    const float v0 = (tid       < len) ? g_ej[b * L_DIM + tid]       : MASKV;
    const float v1 = (tid + 256 < len) ? g_ej[b * L_DIM + tid + 256] : MASKV;
    sej[tid]       = v0;
    sej[tid + 256] = v1;

    // block max of premasked e_j (len >= 1)
    float mv = fmaxf(v0, v1);
#pragma unroll
    for (int o = 16; o; o >>= 1) mv = fmaxf(mv, __shfl_xor_sync(0xffffffffu, mv, o));
    if (lane == 0) smax[warp] = mv;
    __syncthreads();
    float mxej = smax[0];
#pragma unroll
    for (int k = 1; k < 8; k++) mxej = fmaxf(mxej, smax[k]);

    if (i >= len) return;                       // zero row already written

    const float ei   = g_ei[b * L_DIM + i] + __ldg(ba);
    const float mraw = ei + mxej;
    const float m    = fmaxf(mraw, SLOPE * mraw);   // exact row max (monotonic lrelu)

    float4 p[4];
    float s = 0.f;
#pragma unroll
    for (int t = 0; t < 4; t++) {
        const int j0 = t * 128 + lane * 4;
        float4 e4 = *reinterpret_cast<const float4*>(&sej[j0]);

        float v, lr, pe;
        v = ei + e4.x; lr = fmaxf(v, SLOPE * v);
        pe = __expf(lr - m); p[t].x = pe; s += pe;
        v = ei + e4.y; lr = fmaxf(v, SLOPE * v);
        pe = __expf(lr - m); p[t].y = pe; s += pe;
        v = ei + e4.z; lr = fmaxf(v, SLOPE * v);
        pe = __expf(lr - m); p[t].z = pe; s += pe;
        v = ei + e4.w; lr = fmaxf(v, SLOPE * v);
        pe = __expf(lr - m); p[t].w = pe; s += pe;
    }
#pragma unroll
    for (int o = 16; o; o >>= 1) s += __shfl_xor_sync(0xffffffffu, s, o);

    const float inv = 1.f / s;
#pragma unroll
    for (int t = 0; t < 4; t++) {
        float4 r;
        r.x = p[t].x * inv; r.y = p[t].y * inv;
        r.z = p[t].z * inv; r.w = p[t].w * inv;
        orow4[t * 32 + lane] = r;
    }
}

extern "C" void kernel_launch(void* const* d_in, const int* in_sizes, int n_in,
                              void* d_out, int out_size) {
    const float* nf   = (const float*)d_in[0];   // [B, L, D]
    const float* wa   = (const float*)d_in[1];   // [2D]
    const float* ba   = (const float*)d_in[2];   // [1]
    const int*   tlen = (const int*)d_in[3];     // [B]
    float* out = (float*)d_out;                  // [B, L, L]

    const int B = in_sizes[3];
    const int n_rows = B * L_DIM;

    k_proj<<<(n_rows + 7) / 8, 256>>>(nf, wa, tlen, n_rows);

    // k_soft with programmatic dependent launch: its zero-row prologue
    // overlaps k_proj; real work gated by cudaGridDependencySynchronize().
    cudaLaunchConfig_t cfg = {};
    cfg.gridDim  = dim3(L_DIM / 8, (unsigned)B, 1);
    cfg.blockDim = dim3(256, 1, 1);
    cfg.dynamicSmemBytes = 0;
    cfg.stream = 0;
    cudaLaunchAttribute attr[1];
    attr[0].id = cudaLaunchAttributeProgrammaticStreamSerialization;
    attr[0].val.programmaticStreamSerializationAllowed = 1;
    cfg.attrs = attr;
    cfg.numAttrs = 1;
    cudaLaunchKernelEx(&cfg, k_soft, ba, tlen, out);
}